// round 11
// baseline (speedup 1.0000x reference)
#include <cuda_runtime.h>
#include <cuda_bf16.h>

// OneHotEncoder: per-row token histogram, tokens [256, 2048] i32 -> counts [256, 32000] f32,
// pad_idx=0 skipped. `lengths` is dead in the reference.
//
// R6: split phases, but zero with an SM STORE KERNEL (not a memset node).
//  - R4 showed the graph memset path leaves the output NOT L2-resident (its
//    scatter paid 23 MB of DRAM atomic misses at 2914 GB/s). SM stores
//    write-allocate in L2, so a custom zero kernel makes the follow-up
//    REDG.ADD.F32 scatter hit L2 (~1.3 cyc/lane across 184 LTS slices).
//  - All smem-histogram variants (R2/R5) were bound at ~17K dynamic
//    instructions/SM of binning machinery; this path's instruction floor is
//    just the 64K warp-STG.128 store stream + 512K fire-and-forget REDG.

#define VOCAB   32000
#define SEQ_T   2048

// ---------- Phase 1: zero-fill 32.77 MB with a pure STG.128 stream ----------
#define ZBLOCKS  1184          // 8 CTAs/SM * 148
#define ZTHREADS 256

__global__ __launch_bounds__(ZTHREADS)
void onehot_zero_kernel(float4* __restrict__ out4, int n4)
{
    const float4 z = make_float4(0.f, 0.f, 0.f, 0.f);
    int i = blockIdx.x * ZTHREADS + threadIdx.x;
    const int stride = ZBLOCKS * ZTHREADS;          // 303104
    // n4 = 2,048,000 -> ~6.75 iterations per thread
    #pragma unroll 4
    for (; i < n4; i += stride) {
        out4[i] = z;
    }
}

// ---------- Phase 2: scatter non-pad tokens with RED.ADD.F32 ----------
#define STHREADS 1024
#define TOK_PER_THREAD 4

__global__ __launch_bounds__(STHREADS)
void onehot_scatter_kernel(const int* __restrict__ tokens,
                           float* __restrict__ out)
{
    const int g = blockIdx.x * STHREADS + threadIdx.x;     // int4 index
    const int4 t = reinterpret_cast<const int4*>(tokens)[g];

    // 4 tokens per thread, 4 | 2048 -> all four tokens share one row.
    const int row = (g * TOK_PER_THREAD) >> 11;            // / SEQ_T
    float* row_out = out + (size_t)row * VOCAB;

    if (t.x != 0) atomicAdd(row_out + t.x, 1.0f);   // REDG.ADD.F32, no return
    if (t.y != 0) atomicAdd(row_out + t.y, 1.0f);
    if (t.z != 0) atomicAdd(row_out + t.z, 1.0f);
    if (t.w != 0) atomicAdd(row_out + t.w, 1.0f);
}

extern "C" void kernel_launch(void* const* d_in, const int* in_sizes, int n_in,
                              void* d_out, int out_size)
{
    const int* tokens = (const int*)d_in[0];   // [256, 2048] int32
    // d_in[1] = lengths, unused by the reference computation.
    float* out = (float*)d_out;                // [256, 32000] f32

    const int n_tokens = in_sizes[0];                      // 524288
    const int n4       = out_size / 4;                     // 2,048,000 float4

    // Phase 1: zero via SM stores -> output lines end up L2-resident.
    onehot_zero_kernel<<<ZBLOCKS, ZTHREADS>>>(reinterpret_cast<float4*>(out), n4);

    // Phase 2: scatter-add (stream-ordered after phase 1).
    const int grid = n_tokens / TOK_PER_THREAD / STHREADS; // 128
    onehot_scatter_kernel<<<grid, STHREADS>>>(tokens, out);
}

// round 14
// speedup vs baseline: 1.1069x; 1.1069x over previous
#include <cuda_runtime.h>
#include <cuda_bf16.h>
#include <cstdint>

// OneHotEncoder: per-row token histogram, tokens [256, 2048] i32 -> counts [256, 32000] f32,
// pad_idx=0 skipped. `lengths` is dead in the reference.
//
// R7: fused kernel, f32 smem histogram, TMA bulk-store epilogue.
//  - All split-phase variants (R4/R6) pay DRAM misses on the scatter; all fused
//    variants converge to ~9.2-10.3us at L2=31-41% -> store stream is the wall.
//  - So minimize everything around the store stream:
//      * histogram kept directly as f32 in smem (no u16 pack/unpack, no cvt),
//        binned with ATOMS.ADD.F32;
//      * epilogue = ONE cp.async.bulk (TMA 1D smem->gmem, 32000 B) per CTA,
//        issued by a single thread. Bypasses the L1tex STG path and its
//        cross-CTA wavefront-queue contention entirely.
//  - Grid (256 rows x 4 vocab slices), 256 thr, 32 KB smem -> ~6 CTAs/SM,
//    single wave. Output written exactly once, never read.

#define VOCAB    32000
#define SEQ_T    2048
#define NSPLIT   4
#define VSLICE   (VOCAB / NSPLIT)          // 8000 f32 bins per slice
#define SLICE_BYTES (VSLICE * 4)           // 32000 B (16B-aligned)
#define THREADS  256

__global__ __launch_bounds__(THREADS, 6)
void onehot_tma_kernel(const int* __restrict__ tokens,
                       float* __restrict__ out)
{
    __shared__ __align__(16) float hist[VSLICE];   // 32 KB

    const int row   = blockIdx.x;
    const int vbase = blockIdx.y * VSLICE;
    const int tid   = threadIdx.x;

    // --- zero: 2000 float4 / 256 thr -> 8 STS.128 each ---
    float4* h4 = reinterpret_cast<float4*>(hist);
    const float4 z = make_float4(0.f, 0.f, 0.f, 0.f);
    #pragma unroll
    for (int i = tid; i < VSLICE / 4; i += THREADS) {
        h4[i] = z;
    }
    __syncthreads();

    // --- bin in-slice tokens: 512 int4 / 256 thr -> 2 LDG.128 each ---
    const int4* tok4 = reinterpret_cast<const int4*>(tokens + (size_t)row * SEQ_T);
    #pragma unroll
    for (int i = tid; i < SEQ_T / 4; i += THREADS) {
        int4 t = tok4[i];
        // pad (0) rejected explicitly for slice 0; other slices reject it via
        // unsigned underflow in the range check.
        unsigned vx = (unsigned)(t.x - vbase);
        unsigned vy = (unsigned)(t.y - vbase);
        unsigned vz = (unsigned)(t.z - vbase);
        unsigned vw = (unsigned)(t.w - vbase);
        if (t.x != 0 && vx < VSLICE) atomicAdd(&hist[vx], 1.0f);  // ATOMS.ADD.F32
        if (t.y != 0 && vy < VSLICE) atomicAdd(&hist[vy], 1.0f);
        if (t.z != 0 && vz < VSLICE) atomicAdd(&hist[vz], 1.0f);
        if (t.w != 0 && vw < VSLICE) atomicAdd(&hist[vw], 1.0f);
    }
    __syncthreads();

    // --- epilogue: single TMA 1D bulk store of the whole slice ---
    if (tid == 0) {
        // Order the CTA's generic-proxy smem writes before the async-proxy read.
        asm volatile("fence.proxy.async.shared::cta;" ::: "memory");

        uint32_t src;
        asm("{ .reg .u64 t; cvta.to.shared.u64 t, %1; cvt.u32.u64 %0, t; }"
            : "=r"(src) : "l"(hist));
        float* dst = out + (size_t)row * VOCAB + vbase;

        asm volatile(
            "cp.async.bulk.global.shared::cta.bulk_group [%0], [%1], %2;"
            :: "l"(dst), "r"(src), "n"(SLICE_BYTES)
            : "memory");
        asm volatile("cp.async.bulk.commit_group;" ::: "memory");
        asm volatile("cp.async.bulk.wait_group 0;" ::: "memory");
    }
}

extern "C" void kernel_launch(void* const* d_in, const int* in_sizes, int n_in,
                              void* d_out, int out_size)
{
    const int* tokens = (const int*)d_in[0];   // [256, 2048] int32
    // d_in[1] = lengths, unused by the reference computation.
    float* out = (float*)d_out;                // [256, 32000] f32

    const int batch = in_sizes[0] / SEQ_T;     // 256

    dim3 grid(batch, NSPLIT);
    onehot_tma_kernel<<<grid, THREADS>>>(tokens, out);
}

// round 15
// speedup vs baseline: 1.2682x; 1.1458x over previous
#include <cuda_runtime.h>
#include <cuda_bf16.h>

// OneHotEncoder: per-row token histogram, tokens [256, 2048] i32 -> counts [256, 32000] f32,
// pad_idx=0 skipped. `lengths` is dead in the reference.
//
// R8: R2's structure (one CTA per row, u16-packed smem histogram, NSPLIT=1 ->
// minimal chip-wide instruction count) but with 1024 threads/CTA instead of 512.
//  - 2 CTAs/SM x 32 warps = 64 warps/SM = 100% theoretical occupancy (R2 ran
//    at 37.6% -- the measured bound was latency, 1 issue per ~55 cyc/warp).
//  - Per-thread serial work halves: zero = 3.9 STS.128, bin = 1 LDG.64 + ~2
//    packed smem atomics (2xu16 per u32; max count 2048 < 65536, no carry),
//    dump = 7.8 x (LDS.64 + cvt + STG.128).
//  - No vocab slicing: slicing (R5/R7) multiplies bin-phase instructions by
//    NSPLIT and was a net wash.

#define VOCAB   32000
#define SEQ_T   2048
#define NWORDS  (VOCAB / 2)                      // 16000 packed u32 words
#define THREADS 1024
#define SMEM_BYTES (NWORDS * sizeof(unsigned int))  // 64000 B -> 2 CTAs/SM

__global__ __launch_bounds__(THREADS, 2)
void onehot_hist2_kernel(const int* __restrict__ tokens,
                         float* __restrict__ out)
{
    extern __shared__ unsigned int hist[];   // 32000 u16 counters

    const int row = blockIdx.x;
    const int tid = threadIdx.x;

    // --- zero: 4000 uint4 / 1024 thr -> 3.9 STS.128 each ---
    uint4* h4 = reinterpret_cast<uint4*>(hist);
    for (int i = tid; i < NWORDS / 4; i += THREADS) {
        h4[i] = make_uint4(0u, 0u, 0u, 0u);
    }
    __syncthreads();

    // --- bin: one int2 (LDG.64) per thread, ~2 packed smem atomics ---
    const int2 t = reinterpret_cast<const int2*>(tokens + (size_t)row * SEQ_T)[tid];
    if (t.x != 0) atomicAdd(&hist[(unsigned)t.x >> 1], 1u << (((unsigned)t.x & 1u) << 4));
    if (t.y != 0) atomicAdd(&hist[(unsigned)t.y >> 1], 1u << (((unsigned)t.y & 1u) << 4));
    __syncthreads();

    // --- dump: 8000 uint2 / 1024 thr -> 7.8 x (LDS.64 + 4 cvt + STG.128) ---
    float4* out4 = reinterpret_cast<float4*>(out + (size_t)row * VOCAB);
    const uint2* h2 = reinterpret_cast<const uint2*>(hist);
    for (int i = tid; i < NWORDS / 2; i += THREADS) {
        uint2 w = h2[i];
        float4 v;
        v.x = (float)(w.x & 0xFFFFu);
        v.y = (float)(w.x >> 16);
        v.z = (float)(w.y & 0xFFFFu);
        v.w = (float)(w.y >> 16);
        out4[i] = v;
    }
}

extern "C" void kernel_launch(void* const* d_in, const int* in_sizes, int n_in,
                              void* d_out, int out_size)
{
    const int* tokens = (const int*)d_in[0];   // [256, 2048] int32
    // d_in[1] = lengths, unused by the reference computation.
    float* out = (float*)d_out;                // [256, 32000] f32

    const int batch = in_sizes[0] / SEQ_T;     // 256

    // Idempotent host-side config call; capture-safe, no allocation.
    cudaFuncSetAttribute(onehot_hist2_kernel,
                         cudaFuncAttributeMaxDynamicSharedMemorySize,
                         SMEM_BYTES);

    onehot_hist2_kernel<<<batch, THREADS, SMEM_BYTES>>>(tokens, out);
}

// round 17
// speedup vs baseline: 1.2946x; 1.0208x over previous
#include <cuda_runtime.h>
#include <cuda_bf16.h>

// OneHotEncoder: per-row token histogram, tokens [256, 2048] i32 -> counts [256, 32000] f32,
// pad_idx=0 skipped. `lengths` is dead in the reference.
//
// R9: phase-skewed two-row pipeline. The per-SM cost model from R2/R5/R8
// (all ~9.1us regardless of occupancy/slicing) is:
//     ATOMS: 4096 lanes x 2 cyc  (serial per-SM atomic unit)  ~8.2K cyc
//   + L1tex store wavefronts                                   ~3.5K cyc
//   + smem zero/dump                                            ~2K cyc
// all ADDITIVE because barrier-separated phases run in lockstep across the
// resident CTAs. Fix: one CTA per SM owns TWO rows + two 64KB u16-packed
// histograms (128KB smem), and overlaps row0's dump (LDS+STG path) with
// row1's binning (ATOMS path):
//     zero both | bin row0 (all warps) | {dump row0 (warps 0..15) ||
//     bin row1 (warps 16..31)} | dump row1 (all warps)
// Serial path ~11K cyc vs ~14-16K before.

#define VOCAB   32000
#define SEQ_T   2048
#define NWORDS  (VOCAB / 2)                       // 16000 packed u32 / row
#define THREADS 1024
#define SMEM_BYTES (2 * NWORDS * sizeof(unsigned int))   // 128000 B -> 1 CTA/SM

__device__ __forceinline__ void bump(unsigned int* hist, int tok)
{
    // two u16 counters per u32; max count 2048 < 65536 -> no carry possible
    if (tok != 0)
        atomicAdd(&hist[(unsigned)tok >> 1], 1u << (((unsigned)tok & 1u) << 4));
}

__device__ __forceinline__ void dump_half(const unsigned int* hist,
                                          float* row_out, int tid, int nthr)
{
    // NWORDS/2 = 8000 uint2 -> float4 stores
    const uint2* h2 = reinterpret_cast<const uint2*>(hist);
    float4* out4 = reinterpret_cast<float4*>(row_out);
    for (int i = tid; i < NWORDS / 2; i += nthr) {
        uint2 w = h2[i];
        float4 v;
        v.x = (float)(w.x & 0xFFFFu);
        v.y = (float)(w.x >> 16);
        v.z = (float)(w.y & 0xFFFFu);
        v.w = (float)(w.y >> 16);
        out4[i] = v;
    }
}

__global__ __launch_bounds__(THREADS, 1)
void onehot_pipe_kernel(const int* __restrict__ tokens,
                        float* __restrict__ out)
{
    extern __shared__ unsigned int smem[];
    unsigned int* h0 = smem;            // row0 histogram
    unsigned int* h1 = smem + NWORDS;   // row1 histogram

    const int tid  = threadIdx.x;
    const int row0 = blockIdx.x * 2;
    const int row1 = row0 + 1;

    // --- zero both histograms: 8000 uint4 / 1024 thr -> 7.8 STS.128 each ---
    uint4* z4 = reinterpret_cast<uint4*>(smem);
    for (int i = tid; i < (2 * NWORDS) / 4; i += THREADS) {
        z4[i] = make_uint4(0u, 0u, 0u, 0u);
    }
    __syncthreads();

    // --- bin row0 with ALL warps: one int2 per thread ---
    {
        const int2 t = reinterpret_cast<const int2*>(tokens + (size_t)row0 * SEQ_T)[tid];
        bump(h0, t.x);
        bump(h0, t.y);
    }
    __syncthreads();

    // --- overlap: warps 0-15 dump row0 (LDS+STG path) while
    //              warps 16-31 bin row1 (ATOMS path) ---
    if (tid < THREADS / 2) {
        dump_half(h0, out + (size_t)row0 * VOCAB, tid, THREADS / 2);
    } else {
        const int j = tid - THREADS / 2;               // 0..511
        const int4 t = reinterpret_cast<const int4*>(tokens + (size_t)row1 * SEQ_T)[j];
        bump(h1, t.x);
        bump(h1, t.y);
        bump(h1, t.z);
        bump(h1, t.w);
    }
    __syncthreads();

    // --- dump row1 with all warps ---
    dump_half(h1, out + (size_t)row1 * VOCAB, tid, THREADS);
}

extern "C" void kernel_launch(void* const* d_in, const int* in_sizes, int n_in,
                              void* d_out, int out_size)
{
    const int* tokens = (const int*)d_in[0];   // [256, 2048] int32
    // d_in[1] = lengths, unused by the reference computation.
    float* out = (float*)d_out;                // [256, 32000] f32

    const int batch = in_sizes[0] / SEQ_T;     // 256
    const int grid  = batch / 2;               // 128 CTAs, 2 rows each

    // Idempotent host-side config; capture-safe, no allocation.
    cudaFuncSetAttribute(onehot_pipe_kernel,
                         cudaFuncAttributeMaxDynamicSharedMemorySize,
                         SMEM_BYTES);

    onehot_pipe_kernel<<<grid, THREADS, SMEM_BYTES>>>(tokens, out);
}